// round 11
// baseline (speedup 1.0000x reference)
#include <cuda_runtime.h>
#include <cuda_fp16.h>
#include <cstdint>

#define B_ROWS  4096
#define IN_DIM  2048
#define OUT_DIM 2048

// ---------------------------------------------------------------------------
// Device scratch (static globals — no runtime allocation allowed)
// ---------------------------------------------------------------------------
__device__ __half g_Xh [(size_t)B_ROWS  * IN_DIM];       // half(clip(x,±5))   16MB
__device__ __half g_Wth[(size_t)OUT_DIM * IN_DIM];       // half(Ws+Wm+Wf)      8MB
__device__ __half g_P4 [(size_t)4 * B_ROWS * OUT_DIM];   // 4 split-K partials 64MB

// ---------------------------------------------------------------------------
// PTX helpers (family-safe: cp.async, ldmatrix, mma.sync)
// ---------------------------------------------------------------------------
__device__ __forceinline__ uint32_t smem_u32(const void* p) {
    uint32_t a;
    asm("{ .reg .u64 t; cvta.to.shared.u64 t, %1; cvt.u32.u64 %0, t; }"
        : "=r"(a) : "l"(p));
    return a;
}

__device__ __forceinline__ uint32_t h2_bits(__half2 h) {
    return *reinterpret_cast<uint32_t*>(&h);
}

__device__ __forceinline__ void cp_async16(uint32_t dst, const void* src) {
    asm volatile("cp.async.cg.shared.global [%0], [%1], 16;"
                 :: "r"(dst), "l"(src));
}
#define CP_COMMIT() asm volatile("cp.async.commit_group;" ::: "memory")
#define CP_WAIT(n)  asm volatile("cp.async.wait_group %0;" :: "n"(n) : "memory")

#define LDSM_X4(r0, r1, r2, r3, addr)                                         \
    asm volatile("ldmatrix.sync.aligned.m8n8.x4.shared.b16 {%0,%1,%2,%3}, [%4];" \
                 : "=r"(r0), "=r"(r1), "=r"(r2), "=r"(r3) : "r"(addr))

#define MMA_16816(d0, d1, d2, d3, a0, a1, a2, a3, b0, b1)                     \
    asm volatile("mma.sync.aligned.m16n8k16.row.col.f32.f16.f16.f32 "         \
                 "{%0,%1,%2,%3}, {%4,%5,%6,%7}, {%8,%9}, {%0,%1,%2,%3};"      \
                 : "+f"(d0), "+f"(d1), "+f"(d2), "+f"(d3)                     \
                 : "r"(a0), "r"(a1), "r"(a2), "r"(a3), "r"(b0), "r"(b1))

// ---------------------------------------------------------------------------
// Fused prepass. Heavy W-fold blocks first:
//   blocks [0, 2048)    : fold W_slow+W_medium+W_fast -> fp16
//   blocks [2048, 6144) : convert x (clip ±5 -> fp16)
// ---------------------------------------------------------------------------
__global__ void prep_kernel(const float4* __restrict__ x,
                            const float4* __restrict__ ws,
                            const float4* __restrict__ wm,
                            const float4* __restrict__ wf) {
    if (blockIdx.x < 2048) {
        int i = blockIdx.x * blockDim.x + threadIdx.x;
        float4 s0 = ws[2 * i], s1 = ws[2 * i + 1];
        float4 m0 = wm[2 * i], m1 = wm[2 * i + 1];
        float4 f0 = wf[2 * i], f1 = wf[2 * i + 1];
        uint4 ot;
        ot.x = h2_bits(__floats2half2_rn(s0.x + m0.x + f0.x, s0.y + m0.y + f0.y));
        ot.y = h2_bits(__floats2half2_rn(s0.z + m0.z + f0.z, s0.w + m0.w + f0.w));
        ot.z = h2_bits(__floats2half2_rn(s1.x + m1.x + f1.x, s1.y + m1.y + f1.y));
        ot.w = h2_bits(__floats2half2_rn(s1.z + m1.z + f1.z, s1.w + m1.w + f1.w));
        reinterpret_cast<uint4*>(g_Wth)[i] = ot;
    } else {
        int i = (blockIdx.x - 2048) * blockDim.x + threadIdx.x;
        float4 a = x[2 * i], b = x[2 * i + 1];
        a.x = fminf(fmaxf(a.x, -5.0f), 5.0f);  a.y = fminf(fmaxf(a.y, -5.0f), 5.0f);
        a.z = fminf(fmaxf(a.z, -5.0f), 5.0f);  a.w = fminf(fmaxf(a.w, -5.0f), 5.0f);
        b.x = fminf(fmaxf(b.x, -5.0f), 5.0f);  b.y = fminf(fmaxf(b.y, -5.0f), 5.0f);
        b.z = fminf(fmaxf(b.z, -5.0f), 5.0f);  b.w = fminf(fmaxf(b.w, -5.0f), 5.0f);
        uint4 o;
        o.x = h2_bits(__floats2half2_rn(a.x, a.y));
        o.y = h2_bits(__floats2half2_rn(a.z, a.w));
        o.z = h2_bits(__floats2half2_rn(b.x, b.y));
        o.w = h2_bits(__floats2half2_rn(b.z, b.w));
        reinterpret_cast<uint4*>(g_Xh)[i] = o;
    }
}

// ---------------------------------------------------------------------------
// Persistent split-K=4 fp16 mma.sync GEMM.
// 2048 units: unit u -> p = u & 511 (tile: bm=(p&31)*128, bn=(p>>5)*128),
//             ks = u >> 9 (K quarter, chunks [ks*16, ks*16+16)).
// 296 persistent CTAs (one exact wave at occ 2); CTA c handles units
// u = c + t*296. The cp.async ring runs CONTINUOUSLY across unit boundaries:
// flat iteration j -> (unit j>>4, chunk j&15); prefetch decodes j+4.
// Per-unit epilogue writes fp16 partial to g_P4[ks], then accs reset.
// ---------------------------------------------------------------------------
constexpr int BK = 32, STAGES = 5;
constexpr int ASTRIDE = 40;                        // halves per smem row (80B, CF)
constexpr int A_TILE_H  = 128 * ASTRIDE;           // 5120 halves
constexpr int STG_H     = 2 * A_TILE_H;            // 10240
constexpr int SMEM_GEMM = STAGES * STG_H * 2;      // 102400
constexpr int NUNITS   = 2048;
constexpr int NCTAS    = 296;
// 2048 = 296*6 + 272 -> CTAs [0,272) run 7 units, [272,296) run 6.

__global__ __launch_bounds__(256, 2)
void gemm_fp16_persistent() {
    extern __shared__ __half sm[];
    const int tid  = threadIdx.x;
    const int wid  = tid >> 5;
    const int lane = tid & 31;
    const int c    = blockIdx.x;               // [0, 296)
    const int nu   = (c < 272) ? 7 : 6;
    const int niter = nu * 16;

    const int wmBase = (wid & 1) * 64;
    const int wnBase = (wid >> 1) * 32;
    const uint32_t sbase = smem_u32(sm);

    // Loader constants (per-thread slot within the 128x32 tiles)
    const int lrow = tid >> 2;                 // 0..63
    const int lq   = tid & 3;                  // 16B chunk in 64B row
    const size_t aoff = (size_t)lrow * IN_DIM + lq * 8;   // row/col offset within tile
    const uint32_t dA0 = (uint32_t)((lrow      ) * ASTRIDE + lq * 8) * 2;
    const uint32_t dA1 = (uint32_t)((lrow + 64 ) * ASTRIDE + lq * 8) * 2;
    const uint32_t dB0 = dA0 + A_TILE_H * 2;
    const uint32_t dB1 = dA1 + A_TILE_H * 2;

    // Issue the 4 cp.asyncs for flat iteration j into smem stage stg.
    auto load_flat = [&](int stg, int j) {
        const int u  = c + (j >> 4) * NCTAS;
        const int p  = u & 511;
        const int ks = u >> 9;
        const int bm = (p & 31) << 7;
        const int bn = (p >> 5) << 7;
        const int ca = ks * 16 + (j & 15);     // absolute K chunk
        const uint32_t sb = sbase + (uint32_t)stg * STG_H * 2;
        const __half* A  = g_Xh  + (size_t)bm * IN_DIM + aoff + (size_t)ca * BK;
        const __half* Bp = g_Wth + (size_t)bn * IN_DIM + aoff + (size_t)ca * BK;
        cp_async16(sb + dA0, A);
        cp_async16(sb + dA1, A + (size_t)64 * IN_DIM);
        cp_async16(sb + dB0, Bp);
        cp_async16(sb + dB1, Bp + (size_t)64 * IN_DIM);
    };

    const int aRow = wmBase + (lane & 15);
    const int aCol = (lane >> 4) * 8;
    const int bRow = wnBase + (lane & 15);
    const uint32_t aOffBase = (uint32_t)(aRow * ASTRIDE + aCol) * 2;
    const uint32_t bOffBase = (uint32_t)(bRow * ASTRIDE + aCol) * 2 + A_TILE_H * 2;

    const int er = lane >> 2;
    const int ec = (lane & 3) * 2;

    float acc[4][4][4];
#pragma unroll
    for (int i = 0; i < 4; i++)
#pragma unroll
        for (int j = 0; j < 4; j++)
#pragma unroll
            for (int q = 0; q < 4; q++) acc[i][j][q] = 0.0f;

    // One-time prologue
#pragma unroll
    for (int s = 0; s < STAGES - 1; s++) { load_flat(s, s); CP_COMMIT(); }

    int stage = 0, pstage = STAGES - 1;
#pragma unroll 1
    for (int j = 0; j < niter; j++) {
        CP_WAIT(STAGES - 2);
        __syncthreads();
        const int jn = j + STAGES - 1;
        if (jn < niter) load_flat(pstage, jn);
        CP_COMMIT();

        const uint32_t sb = sbase + (uint32_t)stage * STG_H * 2;
        if (++stage == STAGES) stage = 0;
        if (++pstage == STAGES) pstage = 0;

#pragma unroll
        for (int kk = 0; kk < 2; kk++) {
            const uint32_t kOff = (uint32_t)(kk * 16) * 2;
            uint32_t a[4][4];
#pragma unroll
            for (int i = 0; i < 4; i++)
                LDSM_X4(a[i][0], a[i][1], a[i][2], a[i][3],
                        sb + aOffBase + kOff + (uint32_t)(i * 16 * ASTRIDE) * 2);
            uint32_t b[2][4];
#pragma unroll
            for (int jj = 0; jj < 2; jj++)
                LDSM_X4(b[jj][0], b[jj][1], b[jj][2], b[jj][3],
                        sb + bOffBase + kOff + (uint32_t)(jj * 16 * ASTRIDE) * 2);
#pragma unroll
            for (int i = 0; i < 4; i++)
#pragma unroll
                for (int jj = 0; jj < 2; jj++) {
                    MMA_16816(acc[i][2 * jj][0], acc[i][2 * jj][1],
                              acc[i][2 * jj][2], acc[i][2 * jj][3],
                              a[i][0], a[i][1], a[i][2], a[i][3],
                              b[jj][0], b[jj][2]);
                    MMA_16816(acc[i][2 * jj + 1][0], acc[i][2 * jj + 1][1],
                              acc[i][2 * jj + 1][2], acc[i][2 * jj + 1][3],
                              a[i][0], a[i][1], a[i][2], a[i][3],
                              b[jj][1], b[jj][3]);
                }
        }

        // Unit boundary: drain accumulators for the unit just finished.
        if ((j & 15) == 15) {
            const int u  = c + (j >> 4) * NCTAS;
            const int p  = u & 511;
            const int ks = u >> 9;
            const int bm = (p & 31) << 7;
            const int bn = (p >> 5) << 7;
            __half* C = g_P4 + (size_t)ks * B_ROWS * OUT_DIM;
#pragma unroll
            for (int i = 0; i < 4; i++) {
                const int row0 = bm + wmBase + i * 16 + er;
#pragma unroll
                for (int jx = 0; jx < 4; jx++) {
                    const int col = bn + wnBase + jx * 8 + ec;
                    uint32_t v0 = h2_bits(__floats2half2_rn(acc[i][jx][0], acc[i][jx][1]));
                    uint32_t v1 = h2_bits(__floats2half2_rn(acc[i][jx][2], acc[i][jx][3]));
                    *reinterpret_cast<uint32_t*>(C + (size_t)row0 * OUT_DIM + col) = v0;
                    *reinterpret_cast<uint32_t*>(C + (size_t)(row0 + 8) * OUT_DIM + col) = v1;
                    acc[i][jx][0] = 0.0f; acc[i][jx][1] = 0.0f;
                    acc[i][jx][2] = 0.0f; acc[i][jx][3] = 0.0f;
                }
            }
        }
    }
}

// ---------------------------------------------------------------------------
// Fused split-K reduce + LayerNorm + soft clamp.
// Sums the 4 fp16 partials in fp32, then LN + 5*tanh(./5).
// ---------------------------------------------------------------------------
__global__ __launch_bounds__(256)
void ln_tanh_kernel(const float* __restrict__ gamma,
                    const float* __restrict__ beta,
                    float* __restrict__ out) {
    const int row = blockIdx.x;
    constexpr size_t BUFSTRIDE = (size_t)B_ROWS * OUT_DIM;
    const size_t rowOff = (size_t)row * OUT_DIM;

    float p[8] = {0, 0, 0, 0, 0, 0, 0, 0};
#pragma unroll
    for (int ks = 0; ks < 4; ks++) {
        const uint4* p4 = reinterpret_cast<const uint4*>(g_P4 + ks * BUFSTRIDE + rowOff);
        uint4 pv = p4[threadIdx.x];
        float2 f0 = __half22float2(*reinterpret_cast<__half2*>(&pv.x));
        float2 f1 = __half22float2(*reinterpret_cast<__half2*>(&pv.y));
        float2 f2 = __half22float2(*reinterpret_cast<__half2*>(&pv.z));
        float2 f3 = __half22float2(*reinterpret_cast<__half2*>(&pv.w));
        p[0] += f0.x; p[1] += f0.y; p[2] += f1.x; p[3] += f1.y;
        p[4] += f2.x; p[5] += f2.y; p[6] += f3.x; p[7] += f3.y;
    }

    float sum = 0.0f, sq = 0.0f;
#pragma unroll
    for (int q = 0; q < 8; q++) { sum += p[q]; sq += p[q] * p[q]; }

#pragma unroll
    for (int off = 16; off > 0; off >>= 1) {
        sum += __shfl_xor_sync(0xFFFFFFFFu, sum, off);
        sq  += __shfl_xor_sync(0xFFFFFFFFu, sq,  off);
    }
    __shared__ float rs[8], rq[8];
    __shared__ float s_mu, s_inv;
    int lane = threadIdx.x & 31, wrp = threadIdx.x >> 5;
    if (lane == 0) { rs[wrp] = sum; rq[wrp] = sq; }
    __syncthreads();
    if (threadIdx.x == 0) {
        float ts = 0.0f, tq = 0.0f;
#pragma unroll
        for (int i = 0; i < 8; i++) { ts += rs[i]; tq += rq[i]; }
        float mu  = ts * (1.0f / OUT_DIM);
        float var = tq * (1.0f / OUT_DIM) - mu * mu;
        s_mu  = mu;
        s_inv = rsqrtf(fmaxf(var, 0.0f) + 1e-5f);
    }
    __syncthreads();
    const float mu = s_mu, inv = s_inv;

    const float4* g4 = reinterpret_cast<const float4*>(gamma);
    const float4* b4 = reinterpret_cast<const float4*>(beta);
    float4* o4 = reinterpret_cast<float4*>(out + rowOff);

#pragma unroll
    for (int it = 0; it < 2; it++) {
        int j4 = 2 * threadIdx.x + it;
        float4 gv = g4[j4];
        float4 bv = b4[j4];
        float ga[4] = {gv.x, gv.y, gv.z, gv.w};
        float ba[4] = {bv.x, bv.y, bv.z, bv.w};
        float* pp = &p[it * 4];
        float4 ov;
        float* oa = reinterpret_cast<float*>(&ov);
#pragma unroll
        for (int q = 0; q < 4; q++) {
            float nv = (pp[q] - mu) * inv * ga[q] + ba[q];
            float e = __expf(0.4f * nv);
            oa[q] = 5.0f - 10.0f * __frcp_rn(e + 1.0f);
        }
        o4[j4] = ov;
    }
}

// ---------------------------------------------------------------------------
extern "C" void kernel_launch(void* const* d_in, const int* in_sizes, int n_in,
                              void* d_out, int out_size) {
    const float* x     = (const float*)d_in[0];
    const float* Wslow = (const float*)d_in[1];
    const float* Wmed  = (const float*)d_in[2];
    const float* Wfast = (const float*)d_in[3];
    const float* gamma = (const float*)d_in[4];
    const float* beta  = (const float*)d_in[5];
    float* out = (float*)d_out;

    prep_kernel<<<6144, 256>>>(
        reinterpret_cast<const float4*>(x),
        reinterpret_cast<const float4*>(Wslow),
        reinterpret_cast<const float4*>(Wmed),
        reinterpret_cast<const float4*>(Wfast));

    cudaFuncSetAttribute(gemm_fp16_persistent,
                         cudaFuncAttributeMaxDynamicSharedMemorySize, SMEM_GEMM);
    gemm_fp16_persistent<<<NCTAS, 256, SMEM_GEMM>>>();

    ln_tanh_kernel<<<B_ROWS, 256>>>(gamma, beta, out);
}

// round 12
// speedup vs baseline: 1.0230x; 1.0230x over previous
#include <cuda_runtime.h>
#include <cuda_fp16.h>
#include <cstdint>

#define B_ROWS  4096
#define IN_DIM  2048
#define OUT_DIM 2048

// ---------------------------------------------------------------------------
// Device scratch (static globals — no runtime allocation allowed)
// ---------------------------------------------------------------------------
__device__ __half g_Xh [(size_t)B_ROWS  * IN_DIM];       // half(clip(x,±5))   16MB
__device__ __half g_Wth[(size_t)OUT_DIM * IN_DIM];       // half(Ws+Wm+Wf)      8MB
__device__ __half g_P4 [(size_t)4 * B_ROWS * OUT_DIM];   // 4 split-K partials 64MB

// ---------------------------------------------------------------------------
// PTX helpers (family-safe: cp.async, ldmatrix, mma.sync)
// ---------------------------------------------------------------------------
__device__ __forceinline__ uint32_t smem_u32(const void* p) {
    uint32_t a;
    asm("{ .reg .u64 t; cvta.to.shared.u64 t, %1; cvt.u32.u64 %0, t; }"
        : "=r"(a) : "l"(p));
    return a;
}

__device__ __forceinline__ uint32_t h2_bits(__half2 h) {
    return *reinterpret_cast<uint32_t*>(&h);
}

__device__ __forceinline__ void cp_async16(uint32_t dst, const void* src) {
    asm volatile("cp.async.cg.shared.global [%0], [%1], 16;"
                 :: "r"(dst), "l"(src));
}
#define CP_COMMIT() asm volatile("cp.async.commit_group;" ::: "memory")
#define CP_WAIT(n)  asm volatile("cp.async.wait_group %0;" :: "n"(n) : "memory")

#define LDSM_X4(r0, r1, r2, r3, addr)                                         \
    asm volatile("ldmatrix.sync.aligned.m8n8.x4.shared.b16 {%0,%1,%2,%3}, [%4];" \
                 : "=r"(r0), "=r"(r1), "=r"(r2), "=r"(r3) : "r"(addr))

#define MMA_16816(d0, d1, d2, d3, a0, a1, a2, a3, b0, b1)                     \
    asm volatile("mma.sync.aligned.m16n8k16.row.col.f32.f16.f16.f32 "         \
                 "{%0,%1,%2,%3}, {%4,%5,%6,%7}, {%8,%9}, {%0,%1,%2,%3};"      \
                 : "+f"(d0), "+f"(d1), "+f"(d2), "+f"(d3)                     \
                 : "r"(a0), "r"(a1), "r"(a2), "r"(a3), "r"(b0), "r"(b1))

// ---------------------------------------------------------------------------
// Fused prepass. Heavy W-fold blocks first:
//   blocks [0, 2048)    : fold W_slow+W_medium+W_fast -> fp16
//   blocks [2048, 6144) : convert x (clip ±5 -> fp16)
// ---------------------------------------------------------------------------
__global__ void prep_kernel(const float4* __restrict__ x,
                            const float4* __restrict__ ws,
                            const float4* __restrict__ wm,
                            const float4* __restrict__ wf) {
    if (blockIdx.x < 2048) {
        int i = blockIdx.x * blockDim.x + threadIdx.x;
        float4 s0 = ws[2 * i], s1 = ws[2 * i + 1];
        float4 m0 = wm[2 * i], m1 = wm[2 * i + 1];
        float4 f0 = wf[2 * i], f1 = wf[2 * i + 1];
        uint4 ot;
        ot.x = h2_bits(__floats2half2_rn(s0.x + m0.x + f0.x, s0.y + m0.y + f0.y));
        ot.y = h2_bits(__floats2half2_rn(s0.z + m0.z + f0.z, s0.w + m0.w + f0.w));
        ot.z = h2_bits(__floats2half2_rn(s1.x + m1.x + f1.x, s1.y + m1.y + f1.y));
        ot.w = h2_bits(__floats2half2_rn(s1.z + m1.z + f1.z, s1.w + m1.w + f1.w));
        reinterpret_cast<uint4*>(g_Wth)[i] = ot;
    } else {
        int i = (blockIdx.x - 2048) * blockDim.x + threadIdx.x;
        float4 a = x[2 * i], b = x[2 * i + 1];
        a.x = fminf(fmaxf(a.x, -5.0f), 5.0f);  a.y = fminf(fmaxf(a.y, -5.0f), 5.0f);
        a.z = fminf(fmaxf(a.z, -5.0f), 5.0f);  a.w = fminf(fmaxf(a.w, -5.0f), 5.0f);
        b.x = fminf(fmaxf(b.x, -5.0f), 5.0f);  b.y = fminf(fmaxf(b.y, -5.0f), 5.0f);
        b.z = fminf(fmaxf(b.z, -5.0f), 5.0f);  b.w = fminf(fmaxf(b.w, -5.0f), 5.0f);
        uint4 o;
        o.x = h2_bits(__floats2half2_rn(a.x, a.y));
        o.y = h2_bits(__floats2half2_rn(a.z, a.w));
        o.z = h2_bits(__floats2half2_rn(b.x, b.y));
        o.w = h2_bits(__floats2half2_rn(b.z, b.w));
        reinterpret_cast<uint4*>(g_Xh)[i] = o;
    }
}

// ---------------------------------------------------------------------------
// Persistent split-K=4 fp16 GEMM, codegen-clean form.
// 2048 units: u -> p = u & 511 (bm=(p&31)*128, bn=(p>>5)*128), ks = u>>9.
// 296 persistent CTAs; CTA c runs units u = c + t*296 (t < 7 or 6).
// STAGES=4 and 16 chunks/unit => smem stage index (k&3) is COMPILE-TIME in the
// unrolled inner loop. Prefetch distance 3; k>=13 prefetches next unit's
// chunks 0..2, so the cp.async ring never drains. Epilogue per unit is outside
// the inner loop and overlaps the next unit's in-flight loads.
// ---------------------------------------------------------------------------
constexpr int BK = 32, STAGES = 4;
constexpr int ASTRIDE = 40;                        // halves per smem row (80B, CF)
constexpr int A_TILE_H  = 128 * ASTRIDE;           // 5120 halves
constexpr int STG_H     = 2 * A_TILE_H;            // 10240
constexpr int SMEM_GEMM = STAGES * STG_H * 2;      // 81920
constexpr int NCTAS     = 296;

__global__ __launch_bounds__(256, 2)
void gemm_fp16_persistent() {
    extern __shared__ __half sm[];
    const int tid  = threadIdx.x;
    const int wid  = tid >> 5;
    const int lane = tid & 31;
    const int c    = blockIdx.x;               // [0, 296)
    const int nu   = (c < 272) ? 7 : 6;

    const int wmBase = (wid & 1) * 64;
    const int wnBase = (wid >> 1) * 32;
    const uint32_t sbase = smem_u32(sm);

    // Loader slot
    const int lrow = tid >> 2;                 // 0..63
    const int lq   = tid & 3;
    const size_t aoff = (size_t)lrow * IN_DIM + lq * 8;
    const uint32_t dA0 = (uint32_t)((lrow      ) * ASTRIDE + lq * 8) * 2;
    const uint32_t dA1 = (uint32_t)((lrow + 64 ) * ASTRIDE + lq * 8) * 2;
    const uint32_t dB0 = dA0 + A_TILE_H * 2;
    const uint32_t dB1 = dA1 + A_TILE_H * 2;

    // MMA addresses
    const int aRow = wmBase + (lane & 15);
    const int aCol = (lane >> 4) * 8;
    const int bRow = wnBase + (lane & 15);
    const uint32_t aOffBase = (uint32_t)(aRow * ASTRIDE + aCol) * 2;
    const uint32_t bOffBase = (uint32_t)(bRow * ASTRIDE + aCol) * 2 + A_TILE_H * 2;
    const int er = lane >> 2;
    const int ec = (lane & 3) * 2;

    float acc[4][4][4];
#pragma unroll
    for (int i = 0; i < 4; i++)
#pragma unroll
        for (int j = 0; j < 4; j++)
#pragma unroll
            for (int q = 0; q < 4; q++) acc[i][j][q] = 0.0f;

    // Decode unit 0
    int u = c;
    int p = u & 511, ks = u >> 9;
    int bm = (p & 31) << 7, bn = (p >> 5) << 7;
    const __half* Acur = g_Xh  + (size_t)bm * IN_DIM + aoff + (size_t)(ks * 16) * BK;
    const __half* Bcur = g_Wth + (size_t)bn * IN_DIM + aoff + (size_t)(ks * 16) * BK;

    // Prologue: chunks 0..2 of unit 0 into stages 0..2
#pragma unroll
    for (int s = 0; s < STAGES - 1; s++) {
        const uint32_t sb = sbase + (uint32_t)s * STG_H * 2;
        cp_async16(sb + dA0, Acur + s * BK);
        cp_async16(sb + dA1, Acur + s * BK + (size_t)64 * IN_DIM);
        cp_async16(sb + dB0, Bcur + s * BK);
        cp_async16(sb + dB1, Bcur + s * BK + (size_t)64 * IN_DIM);
        CP_COMMIT();
    }

#pragma unroll 1
    for (int t = 0; t < nu; t++) {
        // Decode next unit (pointers used by k>=13 prefetches)
        const bool hasNext = (t + 1 < nu);
        const int un = c + (t + 1) * NCTAS;
        const int pn = un & 511, ksn = un >> 9;
        const int bmn = (pn & 31) << 7, bnn = (pn >> 5) << 7;
        const __half* Anxt = hasNext
            ? g_Xh  + (size_t)bmn * IN_DIM + aoff + (size_t)(ksn * 16) * BK : Acur;
        const __half* Bnxt = hasNext
            ? g_Wth + (size_t)bnn * IN_DIM + aoff + (size_t)(ksn * 16) * BK : Bcur;

#pragma unroll 4
        for (int k = 0; k < 16; k++) {
            CP_WAIT(STAGES - 2);
            __syncthreads();

            // Prefetch chunk k+3 of the continued unit stream
            {
                const bool fromCur = (k < 13);
                const bool doLoad  = fromCur || hasNext;
                if (doLoad) {
                    const __half* A = fromCur ? Acur : Anxt;
                    const __half* B = fromCur ? Bcur : Bnxt;
                    const int kc = fromCur ? (k + 3) : (k - 13);
                    const uint32_t sb = sbase + (uint32_t)((k + 3) & 3) * STG_H * 2;
                    cp_async16(sb + dA0, A + kc * BK);
                    cp_async16(sb + dA1, A + kc * BK + (size_t)64 * IN_DIM);
                    cp_async16(sb + dB0, B + kc * BK);
                    cp_async16(sb + dB1, B + kc * BK + (size_t)64 * IN_DIM);
                }
            }
            CP_COMMIT();

            const uint32_t sb = sbase + (uint32_t)(k & 3) * STG_H * 2;
#pragma unroll
            for (int kk = 0; kk < 2; kk++) {
                const uint32_t kOff = (uint32_t)(kk * 16) * 2;
                uint32_t a[4][4];
#pragma unroll
                for (int i = 0; i < 4; i++)
                    LDSM_X4(a[i][0], a[i][1], a[i][2], a[i][3],
                            sb + aOffBase + kOff + (uint32_t)(i * 16 * ASTRIDE) * 2);
                uint32_t b[2][4];
#pragma unroll
                for (int jj = 0; jj < 2; jj++)
                    LDSM_X4(b[jj][0], b[jj][1], b[jj][2], b[jj][3],
                            sb + bOffBase + kOff + (uint32_t)(jj * 16 * ASTRIDE) * 2);
#pragma unroll
                for (int i = 0; i < 4; i++)
#pragma unroll
                    for (int jj = 0; jj < 2; jj++) {
                        MMA_16816(acc[i][2 * jj][0], acc[i][2 * jj][1],
                                  acc[i][2 * jj][2], acc[i][2 * jj][3],
                                  a[i][0], a[i][1], a[i][2], a[i][3],
                                  b[jj][0], b[jj][2]);
                        MMA_16816(acc[i][2 * jj + 1][0], acc[i][2 * jj + 1][1],
                                  acc[i][2 * jj + 1][2], acc[i][2 * jj + 1][3],
                                  a[i][0], a[i][1], a[i][2], a[i][3],
                                  b[jj][1], b[jj][3]);
                    }
            }
        }

        // Unit epilogue (overlaps next unit's in-flight cp.asyncs)
        {
            __half* C = g_P4 + (size_t)ks * B_ROWS * OUT_DIM;
#pragma unroll
            for (int i = 0; i < 4; i++) {
                const int row0 = bm + wmBase + i * 16 + er;
#pragma unroll
                for (int jx = 0; jx < 4; jx++) {
                    const int col = bn + wnBase + jx * 8 + ec;
                    uint32_t v0 = h2_bits(__floats2half2_rn(acc[i][jx][0], acc[i][jx][1]));
                    uint32_t v1 = h2_bits(__floats2half2_rn(acc[i][jx][2], acc[i][jx][3]));
                    *reinterpret_cast<uint32_t*>(C + (size_t)row0 * OUT_DIM + col) = v0;
                    *reinterpret_cast<uint32_t*>(C + (size_t)(row0 + 8) * OUT_DIM + col) = v1;
                    acc[i][jx][0] = 0.0f; acc[i][jx][1] = 0.0f;
                    acc[i][jx][2] = 0.0f; acc[i][jx][3] = 0.0f;
                }
            }
        }

        // Advance
        Acur = Anxt; Bcur = Bnxt;
        bm = bmn; bn = bnn; ks = ksn;
    }
}

// ---------------------------------------------------------------------------
// Fused split-K reduce + LayerNorm + soft clamp.
// ---------------------------------------------------------------------------
__global__ __launch_bounds__(256)
void ln_tanh_kernel(const float* __restrict__ gamma,
                    const float* __restrict__ beta,
                    float* __restrict__ out) {
    const int row = blockIdx.x;
    constexpr size_t BUFSTRIDE = (size_t)B_ROWS * OUT_DIM;
    const size_t rowOff = (size_t)row * OUT_DIM;

    float p[8] = {0, 0, 0, 0, 0, 0, 0, 0};
#pragma unroll
    for (int ks = 0; ks < 4; ks++) {
        const uint4* p4 = reinterpret_cast<const uint4*>(g_P4 + ks * BUFSTRIDE + rowOff);
        uint4 pv = p4[threadIdx.x];
        float2 f0 = __half22float2(*reinterpret_cast<__half2*>(&pv.x));
        float2 f1 = __half22float2(*reinterpret_cast<__half2*>(&pv.y));
        float2 f2 = __half22float2(*reinterpret_cast<__half2*>(&pv.z));
        float2 f3 = __half22float2(*reinterpret_cast<__half2*>(&pv.w));
        p[0] += f0.x; p[1] += f0.y; p[2] += f1.x; p[3] += f1.y;
        p[4] += f2.x; p[5] += f2.y; p[6] += f3.x; p[7] += f3.y;
    }

    float sum = 0.0f, sq = 0.0f;
#pragma unroll
    for (int q = 0; q < 8; q++) { sum += p[q]; sq += p[q] * p[q]; }

#pragma unroll
    for (int off = 16; off > 0; off >>= 1) {
        sum += __shfl_xor_sync(0xFFFFFFFFu, sum, off);
        sq  += __shfl_xor_sync(0xFFFFFFFFu, sq,  off);
    }
    __shared__ float rs[8], rq[8];
    __shared__ float s_mu, s_inv;
    int lane = threadIdx.x & 31, wrp = threadIdx.x >> 5;
    if (lane == 0) { rs[wrp] = sum; rq[wrp] = sq; }
    __syncthreads();
    if (threadIdx.x == 0) {
        float ts = 0.0f, tq = 0.0f;
#pragma unroll
        for (int i = 0; i < 8; i++) { ts += rs[i]; tq += rq[i]; }
        float mu  = ts * (1.0f / OUT_DIM);
        float var = tq * (1.0f / OUT_DIM) - mu * mu;
        s_mu  = mu;
        s_inv = rsqrtf(fmaxf(var, 0.0f) + 1e-5f);
    }
    __syncthreads();
    const float mu = s_mu, inv = s_inv;

    const float4* g4 = reinterpret_cast<const float4*>(gamma);
    const float4* b4 = reinterpret_cast<const float4*>(beta);
    float4* o4 = reinterpret_cast<float4*>(out + rowOff);

#pragma unroll
    for (int it = 0; it < 2; it++) {
        int j4 = 2 * threadIdx.x + it;
        float4 gv = g4[j4];
        float4 bv = b4[j4];
        float ga[4] = {gv.x, gv.y, gv.z, gv.w};
        float ba[4] = {bv.x, bv.y, bv.z, bv.w};
        float* pp = &p[it * 4];
        float4 ov;
        float* oa = reinterpret_cast<float*>(&ov);
#pragma unroll
        for (int q = 0; q < 4; q++) {
            float nv = (pp[q] - mu) * inv * ga[q] + ba[q];
            float e = __expf(0.4f * nv);
            oa[q] = 5.0f - 10.0f * __frcp_rn(e + 1.0f);
        }
        o4[j4] = ov;
    }
}

// ---------------------------------------------------------------------------
extern "C" void kernel_launch(void* const* d_in, const int* in_sizes, int n_in,
                              void* d_out, int out_size) {
    const float* x     = (const float*)d_in[0];
    const float* Wslow = (const float*)d_in[1];
    const float* Wmed  = (const float*)d_in[2];
    const float* Wfast = (const float*)d_in[3];
    const float* gamma = (const float*)d_in[4];
    const float* beta  = (const float*)d_in[5];
    float* out = (float*)d_out;

    prep_kernel<<<6144, 256>>>(
        reinterpret_cast<const float4*>(x),
        reinterpret_cast<const float4*>(Wslow),
        reinterpret_cast<const float4*>(Wmed),
        reinterpret_cast<const float4*>(Wfast));

    cudaFuncSetAttribute(gemm_fp16_persistent,
                         cudaFuncAttributeMaxDynamicSharedMemorySize, SMEM_GEMM);
    gemm_fp16_persistent<<<NCTAS, 256, SMEM_GEMM>>>();

    ln_tanh_kernel<<<B_ROWS, 256>>>(gamma, beta, out);
}

// round 13
// speedup vs baseline: 1.0915x; 1.0670x over previous
#include <cuda_runtime.h>
#include <cuda_fp16.h>
#include <cstdint>

#define B_ROWS  4096
#define IN_DIM  2048
#define OUT_DIM 2048

// ---------------------------------------------------------------------------
// Device scratch (static globals — no runtime allocation allowed)
// ---------------------------------------------------------------------------
__device__ __half g_Xh [(size_t)B_ROWS  * IN_DIM];   // half(clip(x,±5))   16MB
__device__ __half g_Wth[(size_t)OUT_DIM * IN_DIM];   // half(Ws+Wm+Wf)      8MB
__device__ __half g_Ph [(size_t)B_ROWS  * OUT_DIM];  // half(pre_act)      16MB

// ---------------------------------------------------------------------------
// PTX helpers (family-safe: cp.async, ldmatrix, mma.sync)
// ---------------------------------------------------------------------------
__device__ __forceinline__ uint32_t smem_u32(const void* p) {
    uint32_t a;
    asm("{ .reg .u64 t; cvta.to.shared.u64 t, %1; cvt.u32.u64 %0, t; }"
        : "=r"(a) : "l"(p));
    return a;
}

__device__ __forceinline__ uint32_t h2_bits(__half2 h) {
    return *reinterpret_cast<uint32_t*>(&h);
}

__device__ __forceinline__ void cp_async16(uint32_t dst, const void* src) {
    asm volatile("cp.async.cg.shared.global [%0], [%1], 16;"
                 :: "r"(dst), "l"(src));
}
#define CP_COMMIT() asm volatile("cp.async.commit_group;" ::: "memory")
#define CP_WAIT(n)  asm volatile("cp.async.wait_group %0;" :: "n"(n) : "memory")

#define LDSM_X4(r0, r1, r2, r3, addr)                                         \
    asm volatile("ldmatrix.sync.aligned.m8n8.x4.shared.b16 {%0,%1,%2,%3}, [%4];" \
                 : "=r"(r0), "=r"(r1), "=r"(r2), "=r"(r3) : "r"(addr))

#define MMA_16816(d0, d1, d2, d3, a0, a1, a2, a3, b0, b1)                     \
    asm volatile("mma.sync.aligned.m16n8k16.row.col.f32.f16.f16.f32 "         \
                 "{%0,%1,%2,%3}, {%4,%5,%6,%7}, {%8,%9}, {%0,%1,%2,%3};"      \
                 : "+f"(d0), "+f"(d1), "+f"(d2), "+f"(d3)                     \
                 : "r"(a0), "r"(a1), "r"(a2), "r"(a3), "r"(b0), "r"(b1))

// ---------------------------------------------------------------------------
// Fused prepass. Heavy W-fold blocks first:
//   blocks [0, 2048)    : fold W_slow+W_medium+W_fast -> fp16
//   blocks [2048, 6144) : convert x (clip ±5 -> fp16)
// ---------------------------------------------------------------------------
__global__ void prep_kernel(const float4* __restrict__ x,
                            const float4* __restrict__ ws,
                            const float4* __restrict__ wm,
                            const float4* __restrict__ wf) {
    if (blockIdx.x < 2048) {
        int i = blockIdx.x * blockDim.x + threadIdx.x;
        float4 s0 = ws[2 * i], s1 = ws[2 * i + 1];
        float4 m0 = wm[2 * i], m1 = wm[2 * i + 1];
        float4 f0 = wf[2 * i], f1 = wf[2 * i + 1];
        uint4 ot;
        ot.x = h2_bits(__floats2half2_rn(s0.x + m0.x + f0.x, s0.y + m0.y + f0.y));
        ot.y = h2_bits(__floats2half2_rn(s0.z + m0.z + f0.z, s0.w + m0.w + f0.w));
        ot.z = h2_bits(__floats2half2_rn(s1.x + m1.x + f1.x, s1.y + m1.y + f1.y));
        ot.w = h2_bits(__floats2half2_rn(s1.z + m1.z + f1.z, s1.w + m1.w + f1.w));
        reinterpret_cast<uint4*>(g_Wth)[i] = ot;
    } else {
        int i = (blockIdx.x - 2048) * blockDim.x + threadIdx.x;
        float4 a = x[2 * i], b = x[2 * i + 1];
        a.x = fminf(fmaxf(a.x, -5.0f), 5.0f);  a.y = fminf(fmaxf(a.y, -5.0f), 5.0f);
        a.z = fminf(fmaxf(a.z, -5.0f), 5.0f);  a.w = fminf(fmaxf(a.w, -5.0f), 5.0f);
        b.x = fminf(fmaxf(b.x, -5.0f), 5.0f);  b.y = fminf(fmaxf(b.y, -5.0f), 5.0f);
        b.z = fminf(fmaxf(b.z, -5.0f), 5.0f);  b.w = fminf(fmaxf(b.w, -5.0f), 5.0f);
        uint4 o;
        o.x = h2_bits(__floats2half2_rn(a.x, a.y));
        o.y = h2_bits(__floats2half2_rn(a.z, a.w));
        o.z = h2_bits(__floats2half2_rn(b.x, b.y));
        o.w = h2_bits(__floats2half2_rn(b.z, b.w));
        reinterpret_cast<uint4*>(g_Xh)[i] = o;
    }
}

// ---------------------------------------------------------------------------
// fp16 mma.sync GEMM, 128x64 CTA tile at occupancy 4.
// 1024 CTAs: bm = (b & 31)*128, bn = (b >> 5)*64.
// 128 threads = 4 warps as 2(m) x 2(n); warp tile 64x32 (identical to R8).
// 3-stage cp.async pipeline; occ-4 co-residency supplies latency hiding.
// Wave structure: 592 concurrent (4/SM) -> wave2 432 CTAs all-concurrent at
// <=3/SM, cutting the quantization tail from 0.27T to ~0.06T.
// ---------------------------------------------------------------------------
constexpr int BK = 32, STAGES = 3;
constexpr int ASTRIDE = 40;                        // halves per smem row (80B, CF)
constexpr int A_TILE_H  = 128 * ASTRIDE;           // 5120 halves
constexpr int B_TILE_H  = 64 * ASTRIDE;            // 2560 halves
constexpr int STG_H     = A_TILE_H + B_TILE_H;     // 7680
constexpr int SMEM_GEMM = STAGES * STG_H * 2;      // 46080
constexpr int NCHUNK = IN_DIM / BK;                // 64

__global__ __launch_bounds__(128, 4)
void gemm_fp16_kernel() {
    extern __shared__ __half sm[];
    const int tid  = threadIdx.x;
    const int wid  = tid >> 5;
    const int lane = tid & 31;
    const int bm = (blockIdx.x & 31) << 7;
    const int bn = (blockIdx.x >> 5) << 6;
    const __half* __restrict__ W = g_Wth;

    const int wmBase = (wid & 1) * 64;   // 2 m-warps
    const int wnBase = (wid >> 1) * 32;  // 2 n-warps

    const uint32_t sbase = smem_u32(sm);

    // Loader: A = 512 16B-chunks (4/thread), B = 256 (2/thread).
    // chunk i -> row = i>>2, q = i&3 (16B chunk within 64B row)
    const int arow0 = tid >> 2;          // rows for A chunks: arow0, +32, +64, +96
    const int aq    = tid & 3;
    const int brow0 = tid >> 2;          // rows for B chunks: brow0, +32
    const size_t aoffG = (size_t)aq * 8;
    const __half* gA = g_Xh + (size_t)(bm + arow0) * IN_DIM + aoffG;
    const __half* gB = W    + (size_t)(bn + brow0) * IN_DIM + aoffG;
    const uint32_t dA = (uint32_t)(arow0 * ASTRIDE + aq * 8) * 2;
    const uint32_t dB = (uint32_t)(brow0 * ASTRIDE + aq * 8) * 2 + A_TILE_H * 2;
    constexpr uint32_t AROWSTEP = (uint32_t)(32 * ASTRIDE) * 2;  // +32 rows in smem
    constexpr size_t   GROWSTEP = (size_t)32 * IN_DIM;           // +32 rows in gmem

    auto load_stage = [&](int stage, int chunk) {
        const uint32_t sb = sbase + (uint32_t)stage * STG_H * 2;
        const size_t ko = (size_t)chunk * BK;
#pragma unroll
        for (int j = 0; j < 4; j++)
            cp_async16(sb + dA + j * AROWSTEP, gA + ko + j * GROWSTEP);
#pragma unroll
        for (int j = 0; j < 2; j++)
            cp_async16(sb + dB + j * AROWSTEP, gB + ko + j * GROWSTEP);
    };

    // ldmatrix addresses
    const int aRow = wmBase + (lane & 15);
    const int aCol = (lane >> 4) * 8;
    const int bRow = wnBase + (lane & 15);
    const uint32_t aOffBase = (uint32_t)(aRow * ASTRIDE + aCol) * 2;
    const uint32_t bOffBase = (uint32_t)(bRow * ASTRIDE + aCol) * 2 + A_TILE_H * 2;

    float acc[4][4][4];
#pragma unroll
    for (int i = 0; i < 4; i++)
#pragma unroll
        for (int j = 0; j < 4; j++)
#pragma unroll
            for (int q = 0; q < 4; q++) acc[i][j][q] = 0.0f;

    // Prologue: chunks 0,1 into stages 0,1
#pragma unroll
    for (int s = 0; s < STAGES - 1; s++) { load_stage(s, s); CP_COMMIT(); }

    int stage = 0, pstage = STAGES - 1;
#pragma unroll 1
    for (int k = 0; k < NCHUNK; k++) {
        CP_WAIT(STAGES - 2);
        __syncthreads();
        const int kn = k + STAGES - 1;
        if (kn < NCHUNK) load_stage(pstage, kn);
        CP_COMMIT();

        const uint32_t sb = sbase + (uint32_t)stage * STG_H * 2;
        if (++stage == STAGES) stage = 0;
        if (++pstage == STAGES) pstage = 0;

#pragma unroll
        for (int kk = 0; kk < 2; kk++) {
            const uint32_t kOff = (uint32_t)(kk * 16) * 2;
            uint32_t a[4][4];
#pragma unroll
            for (int i = 0; i < 4; i++)
                LDSM_X4(a[i][0], a[i][1], a[i][2], a[i][3],
                        sb + aOffBase + kOff + (uint32_t)(i * 16 * ASTRIDE) * 2);
            uint32_t b[2][4];
#pragma unroll
            for (int jj = 0; jj < 2; jj++)
                LDSM_X4(b[jj][0], b[jj][1], b[jj][2], b[jj][3],
                        sb + bOffBase + kOff + (uint32_t)(jj * 16 * ASTRIDE) * 2);
#pragma unroll
            for (int i = 0; i < 4; i++)
#pragma unroll
                for (int jj = 0; jj < 2; jj++) {
                    MMA_16816(acc[i][2 * jj][0], acc[i][2 * jj][1],
                              acc[i][2 * jj][2], acc[i][2 * jj][3],
                              a[i][0], a[i][1], a[i][2], a[i][3],
                              b[jj][0], b[jj][2]);
                    MMA_16816(acc[i][2 * jj + 1][0], acc[i][2 * jj + 1][1],
                              acc[i][2 * jj + 1][2], acc[i][2 * jj + 1][3],
                              a[i][0], a[i][1], a[i][2], a[i][3],
                              b[jj][1], b[jj][3]);
                }
        }
    }

    // Epilogue: pack accumulators to fp16, 32-bit stores
    const int er = lane >> 2;
    const int ec = (lane & 3) * 2;
#pragma unroll
    for (int i = 0; i < 4; i++) {
        const int row0 = bm + wmBase + i * 16 + er;
#pragma unroll
        for (int j = 0; j < 4; j++) {
            const int col = bn + wnBase + j * 8 + ec;
            uint32_t v0 = h2_bits(__floats2half2_rn(acc[i][j][0], acc[i][j][1]));
            uint32_t v1 = h2_bits(__floats2half2_rn(acc[i][j][2], acc[i][j][3]));
            *reinterpret_cast<uint32_t*>(g_Ph + (size_t)row0 * OUT_DIM + col) = v0;
            *reinterpret_cast<uint32_t*>(g_Ph + (size_t)(row0 + 8) * OUT_DIM + col) = v1;
        }
    }
}

// ---------------------------------------------------------------------------
// Fused LayerNorm + soft clamp, reading fp16 P (8 halves/thread).
// tanh via saturating exp form: 5*tanh(y/5) = 5 - 10/(exp(0.4y)+1).
// ---------------------------------------------------------------------------
__global__ __launch_bounds__(256)
void ln_tanh_kernel(const float* __restrict__ gamma,
                    const float* __restrict__ beta,
                    float* __restrict__ out) {
    const int row = blockIdx.x;
    const uint4* p4 = reinterpret_cast<const uint4*>(g_Ph + (size_t)row * OUT_DIM);

    uint4 pv = p4[threadIdx.x];
    float2 f0 = __half22float2(*reinterpret_cast<__half2*>(&pv.x));
    float2 f1 = __half22float2(*reinterpret_cast<__half2*>(&pv.y));
    float2 f2 = __half22float2(*reinterpret_cast<__half2*>(&pv.z));
    float2 f3 = __half22float2(*reinterpret_cast<__half2*>(&pv.w));
    float p[8] = {f0.x, f0.y, f1.x, f1.y, f2.x, f2.y, f3.x, f3.y};

    float sum = 0.0f, sq = 0.0f;
#pragma unroll
    for (int q = 0; q < 8; q++) { sum += p[q]; sq += p[q] * p[q]; }

#pragma unroll
    for (int off = 16; off > 0; off >>= 1) {
        sum += __shfl_xor_sync(0xFFFFFFFFu, sum, off);
        sq  += __shfl_xor_sync(0xFFFFFFFFu, sq,  off);
    }
    __shared__ float rs[8], rq[8];
    __shared__ float s_mu, s_inv;
    int lane = threadIdx.x & 31, wrp = threadIdx.x >> 5;
    if (lane == 0) { rs[wrp] = sum; rq[wrp] = sq; }
    __syncthreads();
    if (threadIdx.x == 0) {
        float ts = 0.0f, tq = 0.0f;
#pragma unroll
        for (int i = 0; i < 8; i++) { ts += rs[i]; tq += rq[i]; }
        float mu  = ts * (1.0f / OUT_DIM);
        float var = tq * (1.0f / OUT_DIM) - mu * mu;
        s_mu  = mu;
        s_inv = rsqrtf(fmaxf(var, 0.0f) + 1e-5f);
    }
    __syncthreads();
    const float mu = s_mu, inv = s_inv;

    const float4* g4 = reinterpret_cast<const float4*>(gamma);
    const float4* b4 = reinterpret_cast<const float4*>(beta);
    float4* o4 = reinterpret_cast<float4*>(out + (size_t)row * OUT_DIM);

#pragma unroll
    for (int it = 0; it < 2; it++) {
        int j4 = 2 * threadIdx.x + it;
        float4 gv = g4[j4];
        float4 bv = b4[j4];
        float ga[4] = {gv.x, gv.y, gv.z, gv.w};
        float ba[4] = {bv.x, bv.y, bv.z, bv.w};
        float* pp = &p[it * 4];
        float4 ov;
        float* oa = reinterpret_cast<float*>(&ov);
#pragma unroll
        for (int q = 0; q < 4; q++) {
            float nv = (pp[q] - mu) * inv * ga[q] + ba[q];
            float e = __expf(0.4f * nv);
            oa[q] = 5.0f - 10.0f * __frcp_rn(e + 1.0f);
        }
        o4[j4] = ov;
    }
}

// ---------------------------------------------------------------------------
extern "C" void kernel_launch(void* const* d_in, const int* in_sizes, int n_in,
                              void* d_out, int out_size) {
    const float* x     = (const float*)d_in[0];
    const float* Wslow = (const float*)d_in[1];
    const float* Wmed  = (const float*)d_in[2];
    const float* Wfast = (const float*)d_in[3];
    const float* gamma = (const float*)d_in[4];
    const float* beta  = (const float*)d_in[5];
    float* out = (float*)d_out;

    prep_kernel<<<6144, 256>>>(
        reinterpret_cast<const float4*>(x),
        reinterpret_cast<const float4*>(Wslow),
        reinterpret_cast<const float4*>(Wmed),
        reinterpret_cast<const float4*>(Wfast));

    cudaFuncSetAttribute(gemm_fp16_kernel,
                         cudaFuncAttributeMaxDynamicSharedMemorySize, SMEM_GEMM);
    gemm_fp16_kernel<<<1024, 128, SMEM_GEMM>>>();

    ln_tanh_kernel<<<B_ROWS, 256>>>(gamma, beta, out);
}